// round 2
// baseline (speedup 1.0000x reference)
#include <cuda_runtime.h>

#define B_ 4
#define C_ 64
#define H_ 64
#define W_ 192
#define D_ 24
#define HW_ (H_*W_)

// Feature maps in [vol][b][h][c][w] layout (row-of-image channel-major).
__device__ float g_Q[2][B_][H_][C_][W_];
__device__ float g_K[2][B_][H_][C_][W_];

typedef unsigned long long u64;

__device__ __forceinline__ u64 pack2(float x) {
    unsigned r = __float_as_uint(x);
    u64 p;
    asm("mov.b64 %0, {%1, %1};" : "=l"(p) : "r"(r));
    return p;
}
__device__ __forceinline__ u64 ffma2(u64 a, u64 b, u64 c) {
    u64 d;
    asm("fma.rn.f32x2 %0, %1, %2, %3;" : "=l"(d) : "l"(a), "l"(b), "l"(c));
    return d;
}
__device__ __forceinline__ float2 unpack2(u64 p) {
    unsigned lo, hi;
    asm("mov.b64 {%0, %1}, %2;" : "=r"(lo), "=r"(hi) : "l"(p));
    return make_float2(__uint_as_float(lo), __uint_as_float(hi));
}

// ---------------------------------------------------------------------------
// Conv1x1 as register-tiled GEMM. Block=(h,b,src), 128 threads.
// out[cout][pix] = sum_cin wt[cin][cout] * in[cin][pix], both mats (qw, kw).
// Thread tile: 8 cout x 12 pix, f32x2 packed over cout pairs.
// ---------------------------------------------------------------------------
__global__ __launch_bounds__(128, 2) void conv1x1_kernel(
    const float* __restrict__ x, const float* __restrict__ y,
    const float* __restrict__ qw, const float* __restrict__ qb,
    const float* __restrict__ kw, const float* __restrict__ kb)
{
    extern __shared__ float sm[];
    float* in_s = sm;              // [64 cin][192 pix]
    float* wt_s = sm + 64 * 192;   // [2 mats][64 cin][64 cout]
    const int h = blockIdx.x, b = blockIdx.y, srcIdx = blockIdx.z;
    const float* src = (srcIdx == 0) ? x : y;
    const int tid = threadIdx.x;

    // Load input row h: in_s[cin][w] (coalesced float4 per channel row)
    for (int e4 = tid; e4 < 3072; e4 += 128) {
        int k = e4 / 48, w4 = e4 - k * 48;
        *(float4*)&in_s[k * 192 + w4 * 4] =
            *(const float4*)(src + ((size_t)(b * 64 + k)) * HW_ + h * 192 + w4 * 4);
    }
    // Transposed weights: wt_s[m][cin][cout] = w[cout][cin]
    for (int m = 0; m < 2; ++m) {
        const float* w = m ? kw : qw;
        for (int e4 = tid; e4 < 1024; e4 += 128) {
            int o = e4 >> 4, i4 = e4 & 15;
            float4 v = ((const float4*)w)[e4];
            float* dst = &wt_s[m * 4096 + (i4 * 4) * 64 + o];
            dst[0] = v.x; dst[64] = v.y; dst[128] = v.z; dst[192] = v.w;
        }
    }
    __syncthreads();

    const int tw = tid >> 4;  // 0..7  -> cout base tw*8
    const int tx = tid & 15;  // 0..15 -> pix  base tx*12

    for (int m = 0; m < 2; ++m) {
        const float* A = wt_s + m * 4096;
        u64 acc[4][12];
        #pragma unroll
        for (int i = 0; i < 4; i++)
            #pragma unroll
            for (int j = 0; j < 12; j++) acc[i][j] = 0ull;

        #pragma unroll 2
        for (int k = 0; k < 64; ++k) {
            float4 a0 = *(const float4*)&A[k * 64 + tw * 8];
            float4 a1 = *(const float4*)&A[k * 64 + tw * 8 + 4];
            float4 b0 = *(const float4*)&in_s[k * 192 + tx * 12];
            float4 b1 = *(const float4*)&in_s[k * 192 + tx * 12 + 4];
            float4 b2 = *(const float4*)&in_s[k * 192 + tx * 12 + 8];
            u64 ap[4];
            ap[0] = ((u64*)&a0)[0]; ap[1] = ((u64*)&a0)[1];
            ap[2] = ((u64*)&a1)[0]; ap[3] = ((u64*)&a1)[1];
            float bs[12] = {b0.x, b0.y, b0.z, b0.w, b1.x, b1.y, b1.z, b1.w,
                            b2.x, b2.y, b2.z, b2.w};
            u64 bp[12];
            #pragma unroll
            for (int p = 0; p < 12; p++) bp[p] = pack2(bs[p]);
            #pragma unroll
            for (int i = 0; i < 4; i++)
                #pragma unroll
                for (int p = 0; p < 12; p++)
                    acc[i][p] = ffma2(ap[i], bp[p], acc[i][p]);
        }

        const float* bias = m ? kb : qb;
        float* outp = (m == 0) ? &g_Q[srcIdx][b][h][0][0]
                               : &g_K[srcIdx ^ 1][b][h][0][0];
        #pragma unroll
        for (int i = 0; i < 4; i++) {
            int c0 = tw * 8 + i * 2;
            float bz0 = __ldg(&bias[c0]), bz1 = __ldg(&bias[c0 + 1]);
            #pragma unroll
            for (int p = 0; p < 12; p++) {
                float2 t = unpack2(acc[i][p]);
                outp[c0 * W_ + tx * 12 + p]       = t.x + bz0;
                outp[(c0 + 1) * W_ + tx * 12 + p] = t.y + bz1;
            }
        }
    }
}

// ---------------------------------------------------------------------------
// Cost volume. Block=(h,b,vol), 256 threads.
// Phase A: y-blend K rows -> kbT[64 c][192 x] (validity in weights).
// Per 96-w strip: stage qT[64 c][96 w]; GEMM S[96 w][192 x] (tile 6x12,
// f32x2 over x-pairs); gather epilogue: 2 scalar S reads per output.
// ---------------------------------------------------------------------------
__global__ __launch_bounds__(256, 1) void cost_kernel(
    const float* __restrict__ d1, const float* __restrict__ d2,
    float* __restrict__ out)
{
    extern __shared__ float sm[];
    float* kbT = sm;                    // [64][192]  48KB
    float* qT  = sm + 12288;            // [64][96]   24KB
    float* S   = sm + 12288 + 6144;     // [96][192]  72KB
    const int h = blockIdx.x, b = blockIdx.y, vol = blockIdx.z;
    const int tid = threadIdx.x;

    float ys  = h * (64.0f / 63.0f) - 0.5f;
    float y0f = floorf(ys);
    float ty  = ys - y0f;
    int iy0 = (int)y0f, iy1 = iy0 + 1;
    float wy0 = (iy0 >= 0 && iy0 < H_) ? (1.0f - ty) : 0.0f;
    float wy1 = (iy1 >= 0 && iy1 < H_) ? ty : 0.0f;
    int y0c = min(max(iy0, 0), H_ - 1);
    int y1c = min(max(iy1, 0), H_ - 1);
    const float4* k0 = (const float4*)&g_K[vol][b][y0c][0][0];
    const float4* k1 = (const float4*)&g_K[vol][b][y1c][0][0];
    float4* kb4 = (float4*)kbT;
    for (int e = tid; e < 3072; e += 256) {
        float4 a = k0[e], c = k1[e];
        kb4[e] = make_float4(wy0 * a.x + wy1 * c.x, wy0 * a.y + wy1 * c.y,
                             wy0 * a.z + wy1 * c.z, wy0 * a.w + wy1 * c.w);
    }

    const int tw = tid >> 4;  // 0..15 -> local w base tw*6
    const int tx = tid & 15;  // 0..15 -> x base tx*12
    const float* dispb = ((vol == 0) ? d1 : d2) + (size_t)b * D_ * HW_ + h * W_;
    float* outb = out + ((size_t)(vol * B_ + b) * D_) * HW_ + h * W_;

    for (int s = 0; s < 2; ++s) {
        const int wbase = s * 96;
        // stage Q strip (coalesced; no hazard with blend/gather)
        for (int e4 = tid; e4 < 1536; e4 += 256) {
            int k = e4 / 24, wq = e4 - k * 24;
            *(float4*)&qT[k * 96 + wq * 4] =
                *(const float4*)&g_Q[vol][b][h][k][wbase + wq * 4];
        }
        __syncthreads();   // qT + kbT ready before GEMM; S free (prev gather done)

        u64 acc[6][6];
        #pragma unroll
        for (int i = 0; i < 6; i++)
            #pragma unroll
            for (int j = 0; j < 6; j++) acc[i][j] = 0ull;

        #pragma unroll 2
        for (int k = 0; k < 64; ++k) {
            const float* Ar = &qT[k * 96 + tw * 6];
            float2 a01 = *(const float2*)(Ar);
            float2 a23 = *(const float2*)(Ar + 2);
            float2 a45 = *(const float2*)(Ar + 4);
            float aw[6] = {a01.x, a01.y, a23.x, a23.y, a45.x, a45.y};
            const float* Br = &kbT[k * 192 + tx * 12];
            float4 b0 = *(const float4*)(Br);
            float4 b1 = *(const float4*)(Br + 4);
            float4 b2 = *(const float4*)(Br + 8);
            u64 bp[6];
            bp[0] = ((u64*)&b0)[0]; bp[1] = ((u64*)&b0)[1];
            bp[2] = ((u64*)&b1)[0]; bp[3] = ((u64*)&b1)[1];
            bp[4] = ((u64*)&b2)[0]; bp[5] = ((u64*)&b2)[1];
            u64 ap[6];
            #pragma unroll
            for (int i = 0; i < 6; i++) ap[i] = pack2(aw[i]);
            #pragma unroll
            for (int i = 0; i < 6; i++)
                #pragma unroll
                for (int j = 0; j < 6; j++)
                    acc[i][j] = ffma2(ap[i], bp[j], acc[i][j]);
        }

        // write S strip
        #pragma unroll
        for (int i = 0; i < 6; i++) {
            float* Sr = &S[(tw * 6 + i) * 192 + tx * 12];
            float2 t0 = unpack2(acc[i][0]), t1 = unpack2(acc[i][1]);
            float2 t2 = unpack2(acc[i][2]), t3 = unpack2(acc[i][3]);
            float2 t4 = unpack2(acc[i][4]), t5 = unpack2(acc[i][5]);
            *(float4*)(Sr)     = make_float4(t0.x, t0.y, t1.x, t1.y);
            *(float4*)(Sr + 4) = make_float4(t2.x, t2.y, t3.x, t3.y);
            *(float4*)(Sr + 8) = make_float4(t4.x, t4.y, t5.x, t5.y);
        }
        __syncthreads();

        // gather: 24 d x 96 w outputs for this strip
        #pragma unroll 1
        for (int it = 0; it < 9; ++it) {
            int flat = it * 256 + tid;
            int d  = flat / 96;
            int wl = flat - d * 96;
            float disp = __ldg(&dispb[d * HW_ + wbase + wl]);
            float xs  = disp * (192.0f / 191.0f) - 0.5f;
            float x0f = floorf(xs);
            float txf = xs - x0f;
            int ix0 = (int)x0f;
            float wx0 = (ix0 >= 0 && ix0 < W_) ? (1.0f - txf) : 0.0f;
            float wx1 = (ix0 + 1 >= 0 && ix0 + 1 < W_) ? txf : 0.0f;
            int x0c = min(max(ix0, 0), W_ - 1);
            int x1c = min(max(ix0 + 1, 0), W_ - 1);
            float sv = wx0 * S[wl * 192 + x0c] + wx1 * S[wl * 192 + x1c];
            outb[d * HW_ + wbase + wl] = sv * 0.015625f;
        }
        __syncthreads();   // protect qT/S before next strip overwrites
    }
}

extern "C" void kernel_launch(void* const* d_in, const int* in_sizes, int n_in,
                              void* d_out, int out_size) {
    const float* x  = (const float*)d_in[0];
    const float* y  = (const float*)d_in[1];
    const float* d1 = (const float*)d_in[2];
    const float* d2 = (const float*)d_in[3];
    int wbase = (in_sizes[4] == 1) ? 5 : 4;
    const float* qw = (const float*)d_in[wbase + 0];
    const float* qb = (const float*)d_in[wbase + 1];
    const float* kw = (const float*)d_in[wbase + 2];
    const float* kb = (const float*)d_in[wbase + 3];
    float* out = (float*)d_out;

    cudaFuncSetAttribute(conv1x1_kernel,
                         cudaFuncAttributeMaxDynamicSharedMemorySize, 81920);
    cudaFuncSetAttribute(cost_kernel,
                         cudaFuncAttributeMaxDynamicSharedMemorySize, 147456);

    conv1x1_kernel<<<dim3(H_, B_, 2), 128, 81920>>>(x, y, qw, qb, kw, kb);
    cost_kernel<<<dim3(H_, B_, 2), 256, 147456>>>(d1, d2, out);
}

// round 3
// speedup vs baseline: 1.5599x; 1.5599x over previous
#include <cuda_runtime.h>

#define B_ 4
#define C_ 64
#define H_ 64
#define W_ 192
#define D_ 24
#define HW_ (H_*W_)

// Feature maps [vol][b][h*w][c] (channel-contiguous per pixel).
__device__ float g_Q[2][B_][HW_][C_];
__device__ float g_K[2][B_][HW_][C_];

typedef unsigned long long u64;

__device__ __forceinline__ u64 pack2(float x) {
    unsigned r = __float_as_uint(x);
    u64 p;
    asm("mov.b64 %0, {%1, %1};" : "=l"(p) : "r"(r));
    return p;
}
__device__ __forceinline__ u64 ffma2(u64 a, u64 b, u64 c) {
    u64 d;
    asm("fma.rn.f32x2 %0, %1, %2, %3;" : "=l"(d) : "l"(a), "l"(b), "l"(c));
    return d;
}
__device__ __forceinline__ float2 unpack2(u64 p) {
    unsigned lo, hi;
    asm("mov.b64 {%0, %1}, %2;" : "=r"(lo), "=r"(hi) : "l"(p));
    return make_float2(__uint_as_float(lo), __uint_as_float(hi));
}

// ---------------------------------------------------------------------------
// Conv1x1 GEMM. Block=(h,b,src), 256 threads, tile 8 cout x 6 pix.
// out[pix][cout] = sum_cin wt[cin][cout]*in[cin][pix] + bias, for qw and kw.
// ---------------------------------------------------------------------------
__global__ __launch_bounds__(256, 2) void conv1x1_kernel(
    const float* __restrict__ x, const float* __restrict__ y,
    const float* __restrict__ qw, const float* __restrict__ qb,
    const float* __restrict__ kw, const float* __restrict__ kb)
{
    extern __shared__ float sm[];
    float* in_s = sm;              // [64 cin][192 pix]
    float* wt_s = sm + 12288;      // [2][64 cin][64 cout]
    const int h = blockIdx.x, b = blockIdx.y, srcIdx = blockIdx.z;
    const float* src = (srcIdx == 0) ? x : y;
    const int tid = threadIdx.x;

    for (int e4 = tid; e4 < 3072; e4 += 256) {
        int k = e4 / 48, w4 = e4 - k * 48;
        *(float4*)&in_s[k * 192 + w4 * 4] =
            *(const float4*)(src + ((size_t)(b * 64 + k)) * HW_ + h * 192 + w4 * 4);
    }
    for (int m = 0; m < 2; ++m) {
        const float* w = m ? kw : qw;
        for (int e4 = tid; e4 < 1024; e4 += 256) {
            int o = e4 >> 4, i4 = e4 & 15;
            float4 v = ((const float4*)w)[e4];
            float* dst = &wt_s[m * 4096 + (i4 * 4) * 64 + o];
            dst[0] = v.x; dst[64] = v.y; dst[128] = v.z; dst[192] = v.w;
        }
    }
    __syncthreads();

    const int tw = tid >> 5;   // 0..7  -> cout base tw*8
    const int tx = tid & 31;   // 0..31 -> pix  base tx*6

    for (int m = 0; m < 2; ++m) {
        const float* A = wt_s + m * 4096;
        u64 acc[4][6];
        #pragma unroll
        for (int i = 0; i < 4; i++)
            #pragma unroll
            for (int j = 0; j < 6; j++) acc[i][j] = 0ull;

        #pragma unroll 4
        for (int k = 0; k < 64; ++k) {
            float4 a0 = *(const float4*)&A[k * 64 + tw * 8];
            float4 a1 = *(const float4*)&A[k * 64 + tw * 8 + 4];
            float2 b0 = *(const float2*)&in_s[k * 192 + tx * 6];
            float2 b1 = *(const float2*)&in_s[k * 192 + tx * 6 + 2];
            float2 b2 = *(const float2*)&in_s[k * 192 + tx * 6 + 4];
            u64 ap[4];
            ap[0] = ((u64*)&a0)[0]; ap[1] = ((u64*)&a0)[1];
            ap[2] = ((u64*)&a1)[0]; ap[3] = ((u64*)&a1)[1];
            float bs[6] = {b0.x, b0.y, b1.x, b1.y, b2.x, b2.y};
            u64 bp[6];
            #pragma unroll
            for (int p = 0; p < 6; p++) bp[p] = pack2(bs[p]);
            #pragma unroll
            for (int i = 0; i < 4; i++)
                #pragma unroll
                for (int p = 0; p < 6; p++)
                    acc[i][p] = ffma2(ap[i], bp[p], acc[i][p]);
        }

        const float* bias = m ? kb : qb;
        float* outp = (m == 0) ? &g_Q[srcIdx][b][h * W_][0]
                               : &g_K[srcIdx ^ 1][b][h * W_][0];
        float4 bz0 = *(const float4*)&bias[tw * 8];
        float4 bz1 = *(const float4*)&bias[tw * 8 + 4];
        #pragma unroll
        for (int p = 0; p < 6; p++) {
            float2 t0 = unpack2(acc[0][p]), t1 = unpack2(acc[1][p]);
            float2 t2 = unpack2(acc[2][p]), t3 = unpack2(acc[3][p]);
            float* op = outp + (tx * 6 + p) * 64 + tw * 8;
            *(float4*)op = make_float4(t0.x + bz0.x, t0.y + bz0.y,
                                       t1.x + bz0.z, t1.y + bz0.w);
            *(float4*)(op + 4) = make_float4(t2.x + bz1.x, t2.y + bz1.y,
                                             t3.x + bz1.z, t3.y + bz1.w);
        }
    }
}

// ---------------------------------------------------------------------------
// Cost volume (direct gather, R1 structure). Block=(h,b,vol), 256 threads.
// Prologue: y-blend K rows into kb_s[192 x][64 c] (validity in weights).
// Warp: 4 w-positions x 8 channel-groups; conflict-free LDS.128 gathers.
// Disp loads software-pipelined 8-deep.
// ---------------------------------------------------------------------------
__global__ __launch_bounds__(256, 3) void cost_kernel(
    const float* __restrict__ d1, const float* __restrict__ d2,
    float* __restrict__ out)
{
    __shared__ float kb_s[W_][C_];     // 48 KB
    const int h = blockIdx.x, b = blockIdx.y, vol = blockIdx.z;
    const int tid = threadIdx.x;

    float ys  = h * (64.0f / 63.0f) - 0.5f;
    float y0f = floorf(ys);
    float ty  = ys - y0f;
    int iy0 = (int)y0f, iy1 = iy0 + 1;
    float wy0 = (iy0 >= 0 && iy0 < H_) ? (1.0f - ty) : 0.0f;
    float wy1 = (iy1 >= 0 && iy1 < H_) ? ty : 0.0f;
    int y0c = min(max(iy0, 0), H_ - 1);
    int y1c = min(max(iy1, 0), H_ - 1);
    const float4* k0 = (const float4*)&g_K[vol][b][y0c * W_][0];
    const float4* k1 = (const float4*)&g_K[vol][b][y1c * W_][0];
    float4* kb4 = (float4*)&kb_s[0][0];
    #pragma unroll
    for (int e = tid; e < 3072; e += 256) {
        float4 a = k0[e], c = k1[e];
        kb4[e] = make_float4(wy0 * a.x + wy1 * c.x, wy0 * a.y + wy1 * c.y,
                             wy0 * a.z + wy1 * c.z, wy0 * a.w + wy1 * c.w);
    }
    __syncthreads();

    const int warp = tid >> 5, lane = tid & 31;
    const int wsub = lane >> 3, cg = lane & 7;
    const float* dispb = ((vol == 0) ? d1 : d2) + (size_t)b * D_ * HW_ + h * W_;
    float* outb = out + ((size_t)(vol * B_ + b) * D_) * HW_ + h * W_;

    #pragma unroll 1
    for (int pass = 0; pass < 6; ++pass) {
        const int w = pass * 32 + warp * 4 + wsub;
        const float* qp = &g_Q[vol][b][h * W_ + w][0];
        float4 qA = *(const float4*)(qp + cg * 4);
        float4 qB = *(const float4*)(qp + 32 + cg * 4);
        const float* dp = dispb + w;

        float cur[8];
        #pragma unroll
        for (int j = 0; j < 8; j++) cur[j] = __ldg(dp + j * HW_);

        #pragma unroll 1
        for (int chunk = 0; chunk < 3; ++chunk) {
            float nxt[8];
            if (chunk < 2) {
                #pragma unroll
                for (int j = 0; j < 8; j++)
                    nxt[j] = __ldg(dp + (chunk * 8 + 8 + j) * HW_);
            }
            #pragma unroll
            for (int j = 0; j < 8; j++) {
                const int d = chunk * 8 + j;
                float xs  = cur[j] * (192.0f / 191.0f) - 0.5f;
                float x0f = floorf(xs);
                float txf = xs - x0f;
                int ix0 = (int)x0f;
                float wx0 = (ix0 >= 0 && ix0 < W_) ? (1.0f - txf) : 0.0f;
                float wx1 = (ix0 + 1 >= 0 && ix0 + 1 < W_) ? txf : 0.0f;
                int x0c = min(max(ix0, 0), W_ - 1);
                int x1c = min(max(ix0 + 1, 0), W_ - 1);
                const float* r0 = &kb_s[x0c][0];
                const float* r1 = &kb_s[x1c][0];
                float4 a0 = *(const float4*)(r0 + cg * 4);
                float4 b0 = *(const float4*)(r0 + 32 + cg * 4);
                float4 a1 = *(const float4*)(r1 + cg * 4);
                float4 b1 = *(const float4*)(r1 + 32 + cg * 4);

                float s;
                s  = qA.x * (wx0 * a0.x + wx1 * a1.x);
                s += qA.y * (wx0 * a0.y + wx1 * a1.y);
                s += qA.z * (wx0 * a0.z + wx1 * a1.z);
                s += qA.w * (wx0 * a0.w + wx1 * a1.w);
                s += qB.x * (wx0 * b0.x + wx1 * b1.x);
                s += qB.y * (wx0 * b0.y + wx1 * b1.y);
                s += qB.z * (wx0 * b0.z + wx1 * b1.z);
                s += qB.w * (wx0 * b0.w + wx1 * b1.w);

                s += __shfl_xor_sync(0xffffffffu, s, 1);
                s += __shfl_xor_sync(0xffffffffu, s, 2);
                s += __shfl_xor_sync(0xffffffffu, s, 4);
                if (cg == 0) outb[d * HW_ + w] = s * 0.015625f;
            }
            if (chunk < 2) {
                #pragma unroll
                for (int j = 0; j < 8; j++) cur[j] = nxt[j];
            }
        }
    }
}

extern "C" void kernel_launch(void* const* d_in, const int* in_sizes, int n_in,
                              void* d_out, int out_size) {
    const float* x  = (const float*)d_in[0];
    const float* y  = (const float*)d_in[1];
    const float* d1 = (const float*)d_in[2];
    const float* d2 = (const float*)d_in[3];
    int wbase = (in_sizes[4] == 1) ? 5 : 4;
    const float* qw = (const float*)d_in[wbase + 0];
    const float* qb = (const float*)d_in[wbase + 1];
    const float* kw = (const float*)d_in[wbase + 2];
    const float* kb = (const float*)d_in[wbase + 3];
    float* out = (float*)d_out;

    cudaFuncSetAttribute(conv1x1_kernel,
                         cudaFuncAttributeMaxDynamicSharedMemorySize, 81920);

    conv1x1_kernel<<<dim3(H_, B_, 2), 256, 81920>>>(x, y, qw, qb, kw, kb);
    cost_kernel<<<dim3(H_, B_, 2), 256>>>(d1, d2, out);
}